// round 1
// baseline (speedup 1.0000x reference)
#include <cuda_runtime.h>
#include <cuda_bf16.h>

// LIF activation with hard reset + flat surrogate (forward only):
//   decay[c] = 1 - w_leak[c]
//   gate  = (Vm < 1)                  (strict)
//   Vm    = relu(x[b,t,c] + decay[c] * Vm * gate)
//   spike = (Vm > 1) ? 1 : 0          (strict)
// x: [B,T,C] f32, w_leak: [C] f32, out: [B,T,C] f32
// B=128, T=1000, C=512. Sequential in T, parallel over B*C lanes.
// Memory bound: 512 MB traffic -> ~75us roofline on GB300.

namespace {
constexpr int B = 128;
constexpr int T = 1000;
constexpr int C = 512;
constexpr int C4 = C / 4;     // float4 lanes per row = 128
constexpr int U  = 10;        // T-unroll: keeps 10 independent LDG.128 in flight per thread
constexpr int THREADS = 64;   // 16384 threads total -> 256 blocks (covers 148 SMs)
}

__global__ void __launch_bounds__(THREADS, 8)
lif_kernel(const float4* __restrict__ x4,
           const float4* __restrict__ wl4,
           float4* __restrict__ out4)
{
    const int tid = blockIdx.x * THREADS + threadIdx.x;   // one thread per (b, c4)
    const int c4  = tid & (C4 - 1);
    const int b   = tid >> 7;                              // tid / C4

    // decay = 1 - w_leak (per channel, 4 channels per thread)
    const float4 wl = wl4[c4];
    const float dx = 1.0f - wl.x;
    const float dy = 1.0f - wl.y;
    const float dz = 1.0f - wl.z;
    const float dw = 1.0f - wl.w;

    const size_t row0 = (size_t)b * (size_t)T * (size_t)C4 + (size_t)c4;
    const float4* __restrict__ xr = x4  + row0;
    float4*       __restrict__ orow = out4 + row0;

    float vx = 0.0f, vy = 0.0f, vz = 0.0f, vw = 0.0f;

    for (int t0 = 0; t0 < T; t0 += U) {
        // Batch independent loads first: full MLP, hides DRAM latency.
        float4 xv[U];
        #pragma unroll
        for (int u = 0; u < U; u++)
            xv[u] = xr[(size_t)(t0 + u) * C4];

        #pragma unroll
        for (int u = 0; u < U; u++) {
            // gate: strictly Vm < 1 keeps the decayed membrane; else hard reset to 0
            vx = fmaxf(0.0f, xv[u].x + (vx < 1.0f ? dx * vx : 0.0f));
            vy = fmaxf(0.0f, xv[u].y + (vy < 1.0f ? dy * vy : 0.0f));
            vz = fmaxf(0.0f, xv[u].z + (vz < 1.0f ? dz * vz : 0.0f));
            vw = fmaxf(0.0f, xv[u].w + (vw < 1.0f ? dw * vw : 0.0f));

            float4 s;
            s.x = (vx > 1.0f) ? 1.0f : 0.0f;   // strict: spike only above threshold
            s.y = (vy > 1.0f) ? 1.0f : 0.0f;
            s.z = (vz > 1.0f) ? 1.0f : 0.0f;
            s.w = (vw > 1.0f) ? 1.0f : 0.0f;
            orow[(size_t)(t0 + u) * C4] = s;
        }
    }
}

extern "C" void kernel_launch(void* const* d_in, const int* in_sizes, int n_in,
                              void* d_out, int out_size)
{
    const float4* x4  = (const float4*)d_in[0];   // x [B,T,C]
    const float4* wl4 = (const float4*)d_in[1];   // w_leak [C]
    float4* out4      = (float4*)d_out;           // [B,T,C] f32

    const int total_threads = B * C4;             // 16384
    const int blocks = total_threads / THREADS;   // 256
    lif_kernel<<<blocks, THREADS>>>(x4, wl4, out4);
}